// round 8
// baseline (speedup 1.0000x reference)
#include <cuda_runtime.h>
#include <mma.h>
#include <cstdint>

using namespace nvcuda;

// CSCFCLayer: out[b][n] = sum_{f<64} x[b][(n+f)%C] * kernel[(n+f)%C][n] + bias[n]
// B=128, C=N=8192, F=64, fp32.
//
// v8: TF32 wmma with 2 CTAs/SM (phase overlap).
//  - Grid 256: tile = bid>>1 (64 cols), batch half = bid&1 (64 batches). Adjacent
//    CTAs share weight rows -> L2 hits.
//  - CTA: A [64][132] fp32 x-window (cp.async), B [64][132] banded weights ([n][k]).
//    smem 68KB -> 2 CTAs/SM, 32 warps/SM (50% occ).
//  - 16 warps, each one m16n16k8 tf32 acc tile (16x16 out), 16 K-steps.
//  - Epilogue: store_matrix_sync -> smem, +bias, coalesced float4 STG.

#define CDIM 8192
#define NDIM 8192
#define NT 64
#define BT 64
#define THREADS 512
#define ASTRIDE 132
#define BSTRIDE 132
#define OSTRIDE 68
#define A_FLOATS (BT * ASTRIDE)
#define SMEM_NEED ((A_FLOATS + NT * BSTRIDE) * 4)

extern "C" __global__ void __launch_bounds__(THREADS, 2)
cscfc_wmma_kernel(const float* __restrict__ x,
                  const float* __restrict__ w,
                  const float* __restrict__ bias,
                  float* __restrict__ out)
{
    extern __shared__ float sm[];
    float* As = sm;               // [64][ASTRIDE] x window
    float* Bs = sm + A_FLOATS;    // [64][BSTRIDE] banded weights, [n][k]

    const int tid  = threadIdx.x;
    const int tile = blockIdx.x >> 1;
    const int bh   = blockIdx.x & 1;
    const int n0   = tile * NT;
    const int b0   = bh * BT;

    // ---- A fill: A[b][cl] = x[b0+b][(n0+cl)%C], raw fp32 via 16B cp.async.
    //      2048 float4; wrap is float4-aligned. ----
    {
        const unsigned as_u = (unsigned)__cvta_generic_to_shared(As);
#pragma unroll
        for (int it = 0; it < 4; ++it) {
            const int idx = tid + it * THREADS;
            const int b = idx >> 5;
            const int q = idx & 31;
            const int c = (n0 + q * 4) & (CDIM - 1);
            const unsigned dst = as_u + (unsigned)(b * ASTRIDE + q * 4) * 4u;
            const float* src = x + (size_t)(b0 + b) * CDIM + c;
            asm volatile("cp.async.cg.shared.global [%0], [%1], 16;"
                         :: "r"(dst), "l"(src) : "memory");
        }
        asm volatile("cp.async.commit_group;" ::: "memory");
    }

    // ---- B fill: Bs[n][cl] = kernel[(n0+cl)%C][n0+n] if f = cl-n in [0,64) else 0.
    //      2048 float4 gmem reads (coalesced along n), masked scattered STS.32. ----
#pragma unroll
    for (int it = 0; it < 4; ++it) {
        const int idx = tid + it * THREADS;
        const int cl = idx >> 4;
        const int n  = (idx & 15) * 4;
        const int r  = (n0 + cl) & (CDIM - 1);
        const float4 wv = *(const float4*)(w + (size_t)r * NDIM + n0 + n);
        const float v[4] = {wv.x, wv.y, wv.z, wv.w};
#pragma unroll
        for (int j = 0; j < 4; ++j) {
            const unsigned f = (unsigned)(cl - (n + j));
            Bs[(n + j) * BSTRIDE + cl] = (f < 64u) ? v[j] : 0.0f;
        }
    }
    asm volatile("cp.async.wait_group 0;" ::: "memory");
    __syncthreads();

    // ---- MMA: warp (mw, nw): rows mw*16..+15, cols nw*16..+15. ----
    const int wid = tid >> 5;
    const int mw  = wid & 3;
    const int nw  = wid >> 2;

    wmma::fragment<wmma::accumulator, 16, 16, 8, float> c0;
    wmma::fill_fragment(c0, 0.0f);

#pragma unroll 8
    for (int k8 = 0; k8 < 16; ++k8) {
        wmma::fragment<wmma::matrix_a, 16, 16, 8, wmma::precision::tf32, wmma::row_major> af;
        wmma::fragment<wmma::matrix_b, 16, 16, 8, wmma::precision::tf32, wmma::col_major> bf;
        wmma::load_matrix_sync(af, As + (mw * 16) * ASTRIDE + k8 * 8, ASTRIDE);
        wmma::load_matrix_sync(bf, Bs + (nw * 16) * BSTRIDE + k8 * 8, BSTRIDE);
#pragma unroll
        for (int i = 0; i < af.num_elements; ++i)
            af.x[i] = wmma::__float_to_tf32(af.x[i]);
#pragma unroll
        for (int i = 0; i < bf.num_elements; ++i)
            bf.x[i] = wmma::__float_to_tf32(bf.x[i]);
        wmma::mma_sync(c0, af, bf, c0);
    }
    __syncthreads();   // all warps done reading As/Bs before overlaying os

    // ---- Stage results: os[64][OSTRIDE] overlays As. ----
    float* os = sm;
    wmma::store_matrix_sync(os + (mw * 16) * OSTRIDE + nw * 16, c0, OSTRIDE,
                            wmma::mem_row_major);
    __syncthreads();

    // ---- Output: + bias, coalesced float4 stores (2 per thread). ----
#pragma unroll
    for (int it = 0; it < 2; ++it) {
        const int idx = tid + it * THREADS;
        const int b = idx >> 4;
        const int q = (idx & 15) * 4;
        const float4 v  = *(const float4*)(os + b * OSTRIDE + q);
        const float4 bb = *(const float4*)(bias + n0 + q);
        float4 o;
        o.x = v.x + bb.x;
        o.y = v.y + bb.y;
        o.z = v.z + bb.z;
        o.w = v.w + bb.w;
        *(float4*)(out + (size_t)(b0 + b) * NDIM + n0 + q) = o;
    }
}

extern "C" void kernel_launch(void* const* d_in, const int* in_sizes, int n_in,
                              void* d_out, int out_size) {
    const float* x    = (const float*)d_in[0];
    const float* w    = (const float*)d_in[1];
    const float* bias = (const float*)d_in[2];
    float* out        = (float*)d_out;

    cudaFuncSetAttribute(cscfc_wmma_kernel,
                         cudaFuncAttributeMaxDynamicSharedMemorySize, SMEM_NEED);
    cscfc_wmma_kernel<<<2 * (NDIM / NT), THREADS, SMEM_NEED>>>(x, w, bias, out);
}

// round 9
// speedup vs baseline: 1.3810x; 1.3810x over previous
#include <cuda_runtime.h>
#include <cstdint>

// CSCFCLayer: out[b][n] = sum_{f<64} x[b][(n+f)%C] * kernel[(n+f)%C][n] + bias[n]
// B=128, C=N=8192, F=64, fp32.
//
// v9: raw mma.sync.m16n8k8 TF32 + 1024 threads + cp.async chunk pipeline.
//  - Grid 128 (1 CTA/SM): tile = 64 cols, all 128 batches, K = 128 window.
//  - As [128][132] raw fp32 x (cp.async, 4 commit-groups of 32 k-cols).
//  - Bs [64 n][132 k] banded weights, tf32-rounded at fill (band mask + cvt.rna).
//  - 32 warps: warp (mw, nw) owns 16 rows x 16 cols; per k8 step: 4 LDS.32 A
//    + 4 cvt + 4 LDS.32 B + 2 mma.sync. All LDS conflict-free.
//  - Pipeline: chunk kc MMA gated by cp.async.wait_group(3-kc) + bar.
//  - Epilogue: C frags -> smem float2 (os[128][68]) -> +bias -> float4 STG.

#define CDIM 8192
#define NDIM 8192
#define NT 64
#define THREADS 1024
#define ASTRIDE 132
#define BSTRIDE 132
#define OSTRIDE 68
#define A_FLOATS (128 * ASTRIDE)
#define SMEM_NEED ((A_FLOATS + 64 * BSTRIDE) * 4)

__device__ __forceinline__ uint32_t f2tf(float f) {
    uint32_t r;
    asm("cvt.rna.tf32.f32 %0, %1;" : "=r"(r) : "f"(f));
    return r;
}

__device__ __forceinline__ void mma_tf32(float* c,
                                         uint32_t a0, uint32_t a1,
                                         uint32_t a2, uint32_t a3,
                                         uint32_t b0, uint32_t b1) {
    asm volatile(
        "mma.sync.aligned.m16n8k8.row.col.f32.tf32.tf32.f32 "
        "{%0,%1,%2,%3}, {%4,%5,%6,%7}, {%8,%9}, {%0,%1,%2,%3};"
        : "+f"(c[0]), "+f"(c[1]), "+f"(c[2]), "+f"(c[3])
        : "r"(a0), "r"(a1), "r"(a2), "r"(a3), "r"(b0), "r"(b1));
}

extern "C" __global__ void __launch_bounds__(THREADS, 1)
cscfc_mma_kernel(const float* __restrict__ x,
                 const float* __restrict__ w,
                 const float* __restrict__ bias,
                 float* __restrict__ out)
{
    extern __shared__ float sm[];
    float* As = sm;               // [128][ASTRIDE] raw x window
    float* Bs = sm + A_FLOATS;    // [64][BSTRIDE]  banded tf32 weights, [n][k]

    const int tid  = threadIdx.x;
    const int lane = tid & 31;
    const int wid  = tid >> 5;
    const int n0   = blockIdx.x * NT;

    // ---- A fill: 4 chunks of 32 k-cols, 1 float4/thread/chunk, one commit
    //      group per chunk (pipeline gates). ----
    {
        const unsigned as_u = (unsigned)__cvta_generic_to_shared(As);
        const int b = tid >> 3;
        const int q = tid & 7;
#pragma unroll
        for (int kc = 0; kc < 4; ++kc) {
            const int col = kc * 32 + q * 4;
            const int c = (n0 + col) & (CDIM - 1);
            const unsigned dst = as_u + (unsigned)(b * ASTRIDE + col) * 4u;
            const float* src = x + (size_t)b * CDIM + c;
            asm volatile("cp.async.cg.shared.global [%0], [%1], 16;"
                         :: "r"(dst), "l"(src) : "memory");
            asm volatile("cp.async.commit_group;" ::: "memory");
        }
    }

    // ---- B fill: Bs[n][cl] = tf32(kernel[(n0+cl)%C][n0+n]) if f=cl-n in [0,64) else 0.
    //      2048 float4 LDG (coalesced along n); LDG latency overlaps A cp.asyncs. ----
#pragma unroll
    for (int it = 0; it < 2; ++it) {
        const int idx = tid + it * THREADS;
        const int cl = idx >> 4;
        const int n  = (idx & 15) * 4;
        const int r  = (n0 + cl) & (CDIM - 1);
        const float4 wv = *(const float4*)(w + (size_t)r * NDIM + n0 + n);
        const float v[4] = {wv.x, wv.y, wv.z, wv.w};
#pragma unroll
        for (int j = 0; j < 4; ++j) {
            const unsigned f = (unsigned)(cl - (n + j));
            const float m = (f < 64u) ? v[j] : 0.0f;
            *(uint32_t*)&Bs[(n + j) * BSTRIDE + cl] = f2tf(m);
        }
    }

    // ---- Warp tiling: warp (mw, nw): rows mw*16..+15, cols nw*16..+15. ----
    const int mw = wid & 7;
    const int nw = wid >> 3;
    const int g  = lane >> 2;     // 0..7
    const int tg = lane & 3;      // 0..3

    float acc[2][4] = {{0.f, 0.f, 0.f, 0.f}, {0.f, 0.f, 0.f, 0.f}};

    const float* Ap = As + (mw * 16 + g) * ASTRIDE + tg;
    const uint32_t* Bp0 = (const uint32_t*)(Bs + (nw * 16 + g) * BSTRIDE + tg);
    const uint32_t* Bp1 = (const uint32_t*)(Bs + (nw * 16 + 8 + g) * BSTRIDE + tg);

#pragma unroll
    for (int kc = 0; kc < 4; ++kc) {
        // Gate: chunk kc's cp.async group complete, visible to all threads.
        if (kc == 0)      asm volatile("cp.async.wait_group 3;" ::: "memory");
        else if (kc == 1) asm volatile("cp.async.wait_group 2;" ::: "memory");
        else if (kc == 2) asm volatile("cp.async.wait_group 1;" ::: "memory");
        else              asm volatile("cp.async.wait_group 0;" ::: "memory");
        __syncthreads();

#pragma unroll
        for (int s = 0; s < 4; ++s) {
            const int k0 = kc * 32 + s * 8;
            const uint32_t a0 = f2tf(Ap[k0]);
            const uint32_t a1 = f2tf(Ap[8 * ASTRIDE + k0]);
            const uint32_t a2 = f2tf(Ap[k0 + 4]);
            const uint32_t a3 = f2tf(Ap[8 * ASTRIDE + k0 + 4]);
            const uint32_t b0 = Bp0[k0];
            const uint32_t b1 = Bp0[k0 + 4];
            const uint32_t b2 = Bp1[k0];
            const uint32_t b3 = Bp1[k0 + 4];
            mma_tf32(acc[0], a0, a1, a2, a3, b0, b1);
            mma_tf32(acc[1], a0, a1, a2, a3, b2, b3);
        }
    }
    __syncthreads();   // all reads of As/Bs done before os overlay

    // ---- Stage C frags: os[128][OSTRIDE] overlays As.
    //      c0,c1 = (row, col), (row, col+1); c2,c3 = row+8. ----
    float* os = sm;
    {
        const int row = mw * 16 + g;
#pragma unroll
        for (int nt = 0; nt < 2; ++nt) {
            const int col = nw * 16 + nt * 8 + tg * 2;
            *(float2*)&os[row * OSTRIDE + col]       = make_float2(acc[nt][0], acc[nt][1]);
            *(float2*)&os[(row + 8) * OSTRIDE + col] = make_float2(acc[nt][2], acc[nt][3]);
        }
    }
    __syncthreads();

    // ---- Output: + bias, coalesced float4 stores (2 per thread). ----
#pragma unroll
    for (int it = 0; it < 2; ++it) {
        const int idx = tid + it * THREADS;
        const int b = idx >> 4;
        const int q = (idx & 15) * 4;
        const float4 v  = *(const float4*)(os + b * OSTRIDE + q);
        const float4 bb = *(const float4*)(bias + n0 + q);
        float4 o;
        o.x = v.x + bb.x;
        o.y = v.y + bb.y;
        o.z = v.z + bb.z;
        o.w = v.w + bb.w;
        *(float4*)(out + (size_t)b * NDIM + n0 + q) = o;
    }
}

extern "C" void kernel_launch(void* const* d_in, const int* in_sizes, int n_in,
                              void* d_out, int out_size) {
    const float* x    = (const float*)d_in[0];
    const float* w    = (const float*)d_in[1];
    const float* bias = (const float*)d_in[2];
    float* out        = (float*)d_out;

    cudaFuncSetAttribute(cscfc_mma_kernel,
                         cudaFuncAttributeMaxDynamicSharedMemorySize, SMEM_NEED);
    cscfc_mma_kernel<<<NDIM / NT, THREADS, SMEM_NEED>>>(x, w, bias, out);
}

// round 10
// speedup vs baseline: 1.7249x; 1.2491x over previous
#include <cuda_runtime.h>
#include <cstdint>

// CSCFCLayer: out[b][n] = sum_{f<64} x[b][(n+f)%C] * kernel[(n+f)%C][n] + bias[n]
// B=128, C=N=8192, F=64, fp32.
//
// v10 = v9 (raw mma.sync.m16n8k8 tf32, 1024 thr, grid 128) +
//  - band-trimmed mainloop: warp (mw,nw) runs k8 = 2nw .. 2nw+9 (10 steps, not 16);
//    skipped steps have all-zero B (band mask) -> exact.
//  - A operands fed as raw fp32 bits (tf32 truncation; no cvt, shorter dep chain).
//  - B fill: predicated LDG skips fully-out-of-band float4s (w traffic halved).
//  - os in its own smem region (no overlay barrier); bias prefetched to regs.
//  - single cp.async commit group.

#define CDIM 8192
#define NDIM 8192
#define NT 64
#define THREADS 1024
#define ASTRIDE 132
#define BSTRIDE 132
#define OSTRIDE 68
#define A_FLOATS (128 * ASTRIDE)
#define B_FLOATS (64 * BSTRIDE)
#define SMEM_NEED ((A_FLOATS + B_FLOATS + 128 * OSTRIDE) * 4)

__device__ __forceinline__ uint32_t f2tf(float f) {
    uint32_t r;
    asm("cvt.rna.tf32.f32 %0, %1;" : "=r"(r) : "f"(f));
    return r;
}

__device__ __forceinline__ void mma_tf32(float* c,
                                         uint32_t a0, uint32_t a1,
                                         uint32_t a2, uint32_t a3,
                                         uint32_t b0, uint32_t b1) {
    asm volatile(
        "mma.sync.aligned.m16n8k8.row.col.f32.tf32.tf32.f32 "
        "{%0,%1,%2,%3}, {%4,%5,%6,%7}, {%8,%9}, {%0,%1,%2,%3};"
        : "+f"(c[0]), "+f"(c[1]), "+f"(c[2]), "+f"(c[3])
        : "r"(a0), "r"(a1), "r"(a2), "r"(a3), "r"(b0), "r"(b1));
}

extern "C" __global__ void __launch_bounds__(THREADS, 1)
cscfc_mma_kernel(const float* __restrict__ x,
                 const float* __restrict__ w,
                 const float* __restrict__ bias,
                 float* __restrict__ out)
{
    extern __shared__ float sm[];
    float* As = sm;                          // [128][ASTRIDE] raw fp32 x window
    float* Bs = sm + A_FLOATS;               // [64][BSTRIDE]  banded tf32 weights [n][k]
    float* os = sm + A_FLOATS + B_FLOATS;    // [128][OSTRIDE] result staging

    const int tid  = threadIdx.x;
    const int lane = tid & 31;
    const int wid  = tid >> 5;
    const int n0   = blockIdx.x * NT;

    // ---- A fill: raw x window via 16B cp.async (4 per thread, one group). ----
    {
        const unsigned as_u = (unsigned)__cvta_generic_to_shared(As);
        const int b = tid >> 3;
        const int q = tid & 7;
#pragma unroll
        for (int kc = 0; kc < 4; ++kc) {
            const int col = kc * 32 + q * 4;
            const int c = (n0 + col) & (CDIM - 1);
            const unsigned dst = as_u + (unsigned)(b * ASTRIDE + col) * 4u;
            const float* src = x + (size_t)b * CDIM + c;
            asm volatile("cp.async.cg.shared.global [%0], [%1], 16;"
                         :: "r"(dst), "l"(src) : "memory");
        }
        asm volatile("cp.async.commit_group;" ::: "memory");
    }

    // ---- bias prefetch (same cols for both epilogue iterations). ----
    const int oq = (tid & 15) * 4;
    const float4 bb = *(const float4*)(bias + n0 + oq);

    // ---- B fill: Bs[n][cl] = tf32(kernel[(n0+cl)%C][n0+n]) banded; predicated
    //      LDG skips float4s fully outside the band. ----
#pragma unroll
    for (int it = 0; it < 2; ++it) {
        const int idx = tid + it * THREADS;
        const int cl = idx >> 4;
        const int nb = (idx & 15) * 4;
        const int r  = (n0 + cl) & (CDIM - 1);
        const bool va = (cl >= nb) && (cl <= nb + 66);   // any of n=nb..nb+3 in band
        const float4 wv = va ? *(const float4*)(w + (size_t)r * NDIM + n0 + nb)
                             : make_float4(0.f, 0.f, 0.f, 0.f);
        const float v[4] = {wv.x, wv.y, wv.z, wv.w};
#pragma unroll
        for (int j = 0; j < 4; ++j) {
            const unsigned f = (unsigned)(cl - (nb + j));
            const float m = (f < 64u) ? v[j] : 0.0f;
            *(uint32_t*)&Bs[(nb + j) * BSTRIDE + cl] = f2tf(m);
        }
    }
    asm volatile("cp.async.wait_group 0;" ::: "memory");
    __syncthreads();

    // ---- Mainloop: warp (mw, nw): rows mw*16..+15, cols nw*16..+15,
    //      k8 steps 2nw .. 2nw+9 only (band-trimmed). ----
    const int mw = wid & 7;
    const int nw = wid >> 3;
    const int g  = lane >> 2;
    const int tg = lane & 3;

    float acc[2][4] = {{0.f, 0.f, 0.f, 0.f}, {0.f, 0.f, 0.f, 0.f}};

    const float*    Ap  = As + (mw * 16 + g) * ASTRIDE + tg + nw * 16;
    const uint32_t* Bp0 = (const uint32_t*)(Bs + (nw * 16 + g) * BSTRIDE + tg) + nw * 16;
    const uint32_t* Bp1 = (const uint32_t*)(Bs + (nw * 16 + 8 + g) * BSTRIDE + tg) + nw * 16;

#pragma unroll
    for (int s = 0; s < 10; ++s) {
        const int k0 = s * 8;
        const uint32_t a0 = __float_as_uint(Ap[k0]);                 // raw bits = tf32 trunc
        const uint32_t a1 = __float_as_uint(Ap[8 * ASTRIDE + k0]);
        const uint32_t a2 = __float_as_uint(Ap[k0 + 4]);
        const uint32_t a3 = __float_as_uint(Ap[8 * ASTRIDE + k0 + 4]);
        const uint32_t b0 = Bp0[k0];
        const uint32_t b1 = Bp0[k0 + 4];
        const uint32_t b2 = Bp1[k0];
        const uint32_t b3 = Bp1[k0 + 4];
        mma_tf32(acc[0], a0, a1, a2, a3, b0, b1);
        mma_tf32(acc[1], a0, a1, a2, a3, b2, b3);
    }

    // ---- Stage C frags to os (own region -> no pre-barrier needed). ----
    {
        const int row = mw * 16 + g;
#pragma unroll
        for (int nt = 0; nt < 2; ++nt) {
            const int col = nw * 16 + nt * 8 + tg * 2;
            *(float2*)&os[row * OSTRIDE + col]       = make_float2(acc[nt][0], acc[nt][1]);
            *(float2*)&os[(row + 8) * OSTRIDE + col] = make_float2(acc[nt][2], acc[nt][3]);
        }
    }
    __syncthreads();

    // ---- Output: + bias, coalesced float4 stores (2 per thread). ----
#pragma unroll
    for (int it = 0; it < 2; ++it) {
        const int idx = tid + it * THREADS;
        const int b = idx >> 4;
        const float4 v = *(const float4*)(os + b * OSTRIDE + oq);
        float4 o;
        o.x = v.x + bb.x;
        o.y = v.y + bb.y;
        o.z = v.z + bb.z;
        o.w = v.w + bb.w;
        *(float4*)(out + (size_t)b * NDIM + n0 + oq) = o;
    }
}

extern "C" void kernel_launch(void* const* d_in, const int* in_sizes, int n_in,
                              void* d_out, int out_size) {
    const float* x    = (const float*)d_in[0];
    const float* w    = (const float*)d_in[1];
    const float* bias = (const float*)d_in[2];
    float* out        = (float*)d_out;

    cudaFuncSetAttribute(cscfc_mma_kernel,
                         cudaFuncAttributeMaxDynamicSharedMemorySize, SMEM_NEED);
    cscfc_mma_kernel<<<NDIM / NT, THREADS, SMEM_NEED>>>(x, w, bias, out);
}